// round 8
// baseline (speedup 1.0000x reference)
#include <cuda_runtime.h>
#include <cuda_fp16.h>
#include <cuda_bf16.h>

// Problem shapes (fixed by the dataset):
//   text:        [16, 2048, 256] f32      d_in[0]
//   const_mat:   [16, 2048, 2048] i32     d_in[1]   (UNUSED: softmax rows sum to 1)
//   const_labels:[16, 2048, 8] i32        d_in[2]
//   emb_table:   [100, 128] f32           d_in[3]
//   attn_W:      [256, 384] f32           d_in[4]   (UNUSED: cancels in softmax)
//   attn_b:      [256] f32                d_in[5]   (UNUSED)
//   fc_W:        [256, 128] f32           d_in[6]
//   fc_b:        [256] f32                d_in[7]
//   out:         [16, 2048, 256] f32
//
// Collapse: out[pos,d] = relu( text[pos,d] + sum_{k=0..7} G[labels[pos,k], d] )
// with G[n,d] = 0.125 * (fc_b[d] + emb_table[n] . fc_W[d]), G stored fp16.
//
// R8 vs R7: PDL overlap. build_G triggers programmatic launch completion after
// its store; the fused kernel launches with the PDL attribute, front-runs its
// label+text loads (independent of G), then grid-dependency-syncs before the
// G gathers. Hides build_G + the inter-node gap (~5 us of the 19 us total).

#define CN    100
#define CD    128
#define DIM   256
#define KLBL  8

__device__ __half g_Gh[CN * DIM];  // 50 KB fp16 table

// ---------------------------------------------------------------------------
// Kernel A: G[n,d] = 0.125 * (fc_b[d] + sum_c emb_table[n,c] * fc_W[d,c]) -> fp16
// ---------------------------------------------------------------------------
__global__ void __launch_bounds__(DIM) build_G_kernel(
    const float* __restrict__ emb_table,
    const float* __restrict__ fc_W,
    const float* __restrict__ fc_b)
{
    __shared__ float se[CD];
    const int n = blockIdx.x;
    const int d = threadIdx.x;
    if (d < CD) se[d] = emb_table[n * CD + d];
    __syncthreads();

    const float4* w4 = reinterpret_cast<const float4*>(fc_W + d * CD);
    float acc = fc_b[d];
    #pragma unroll
    for (int c4 = 0; c4 < CD / 4; c4++) {
        float4 w = __ldg(w4 + c4);
        acc = fmaf(se[c4 * 4 + 0], w.x, acc);
        acc = fmaf(se[c4 * 4 + 1], w.y, acc);
        acc = fmaf(se[c4 * 4 + 2], w.z, acc);
        acc = fmaf(se[c4 * 4 + 3], w.w, acc);
    }
    g_Gh[n * DIM + d] = __float2half_rn(0.125f * acc);

    // Writes above are visible to the dependent grid after its
    // cudaGridDependencySynchronize().
    cudaTriggerProgrammaticLaunchCompletion();
}

// ---------------------------------------------------------------------------
// Kernel B: fused gather-add-relu. gid -> pos = gid>>5, d4 = gid&31.
// Thread covers output float4s (pos, d4) and (pos, d4+32).
// ---------------------------------------------------------------------------
__device__ __forceinline__ __half2 as_h2(unsigned u) {
    return *reinterpret_cast<const __half2*>(&u);
}

__device__ __forceinline__ float4 reduce8(
    const uint2& u0, const uint2& u1, const uint2& u2, const uint2& u3,
    const uint2& u4, const uint2& u5, const uint2& u6, const uint2& u7,
    const float4& t)
{
    // One HADD2 level in fp16, then fp32 finish.
    const __half2 p0lo = __hadd2(as_h2(u0.x), as_h2(u1.x));
    const __half2 p0hi = __hadd2(as_h2(u0.y), as_h2(u1.y));
    const __half2 p1lo = __hadd2(as_h2(u2.x), as_h2(u3.x));
    const __half2 p1hi = __hadd2(as_h2(u2.y), as_h2(u3.y));
    const __half2 p2lo = __hadd2(as_h2(u4.x), as_h2(u5.x));
    const __half2 p2hi = __hadd2(as_h2(u4.y), as_h2(u5.y));
    const __half2 p3lo = __hadd2(as_h2(u6.x), as_h2(u7.x));
    const __half2 p3hi = __hadd2(as_h2(u6.y), as_h2(u7.y));

    const float2 f0lo = __half22float2(p0lo);
    const float2 f1lo = __half22float2(p1lo);
    const float2 f2lo = __half22float2(p2lo);
    const float2 f3lo = __half22float2(p3lo);
    const float2 f0hi = __half22float2(p0hi);
    const float2 f1hi = __half22float2(p1hi);
    const float2 f2hi = __half22float2(p2hi);
    const float2 f3hi = __half22float2(p3hi);

    float4 r;
    r.x = fmaxf(t.x + (f0lo.x + f1lo.x) + (f2lo.x + f3lo.x), 0.0f);
    r.y = fmaxf(t.y + (f0lo.y + f1lo.y) + (f2lo.y + f3lo.y), 0.0f);
    r.z = fmaxf(t.z + (f0hi.x + f1hi.x) + (f2hi.x + f3hi.x), 0.0f);
    r.w = fmaxf(t.w + (f0hi.y + f1hi.y) + (f2hi.y + f3hi.y), 0.0f);
    return r;
}

__global__ void __launch_bounds__(256, 6) fused_gather_kernel(
    const float4* __restrict__ text4,
    const int*    __restrict__ labels,
    float4*       __restrict__ out4,
    int nhalf)   // number of (pos, d4<32) slots = npos*32
{
    const int gid = blockIdx.x * blockDim.x + threadIdx.x;
    if (gid >= nhalf) return;

    const int pos = gid >> 5;        // warp-uniform (warp = one position)
    const int d4  = gid & 31;        // uint2 slot 0..31; twin at d4+32

    // ---- Phase 1: loads independent of build_G (may run before it finishes)
    const int4* lb = reinterpret_cast<const int4*>(labels) + (pos << 1);
    const int4 l0 = __ldg(lb + 0);
    const int4 l1 = __ldg(lb + 1);

    const int idxA = (pos << 6) + d4;        // output float4 index, low half
    const int idxB = idxA + 32;              // high half

    const float4 tA = __ldg(text4 + idxA);
    const float4 tB = __ldg(text4 + idxB);

    // ---- Wait for build_G's writes to g_Gh to be visible.
    cudaGridDependencySynchronize();

    const uint2* __restrict__ Gh = reinterpret_cast<const uint2*>(g_Gh);

    const int b0 = (l0.x << 6) + d4;
    const int b1 = (l0.y << 6) + d4;
    const int b2 = (l0.z << 6) + d4;
    const int b3 = (l0.w << 6) + d4;
    const int b4 = (l1.x << 6) + d4;
    const int b5 = (l1.y << 6) + d4;
    const int b6 = (l1.z << 6) + d4;
    const int b7 = (l1.w << 6) + d4;

    const uint2 a0 = __ldg(Gh + b0);
    const uint2 a1 = __ldg(Gh + b1);
    const uint2 a2 = __ldg(Gh + b2);
    const uint2 a3 = __ldg(Gh + b3);
    const uint2 a4 = __ldg(Gh + b4);
    const uint2 a5 = __ldg(Gh + b5);
    const uint2 a6 = __ldg(Gh + b6);
    const uint2 a7 = __ldg(Gh + b7);

    const uint2 c0 = __ldg(Gh + b0 + 32);
    const uint2 c1 = __ldg(Gh + b1 + 32);
    const uint2 c2 = __ldg(Gh + b2 + 32);
    const uint2 c3 = __ldg(Gh + b3 + 32);
    const uint2 c4 = __ldg(Gh + b4 + 32);
    const uint2 c5 = __ldg(Gh + b5 + 32);
    const uint2 c6 = __ldg(Gh + b6 + 32);
    const uint2 c7 = __ldg(Gh + b7 + 32);

    const float4 rA = reduce8(a0, a1, a2, a3, a4, a5, a6, a7, tA);
    const float4 rB = reduce8(c0, c1, c2, c3, c4, c5, c6, c7, tB);

    __stcs(out4 + idxA, rA);
    __stcs(out4 + idxB, rB);
}

// ---------------------------------------------------------------------------
extern "C" void kernel_launch(void* const* d_in, const int* in_sizes, int n_in,
                              void* d_out, int out_size)
{
    const float* text      = (const float*)d_in[0];
    const int*   labels    = (const int*)  d_in[2];
    const float* emb_table = (const float*)d_in[3];
    const float* fc_W      = (const float*)d_in[6];
    const float* fc_b      = (const float*)d_in[7];
    float*       out       = (float*)d_out;

    const int ntotal = in_sizes[0];        // 8,388,608
    const int nhalf  = ntotal / 8;         // 1,048,576 threads (2 float4 each)

    build_G_kernel<<<CN, DIM>>>(emb_table, fc_W, fc_b);

    // Fused kernel with programmatic dependent launch: overlaps its
    // label/text prologue with build_G's tail.
    const int block = 256;
    const int grid  = (nhalf + block - 1) / block;   // 4096

    cudaLaunchConfig_t cfg = {};
    cfg.gridDim  = dim3(grid, 1, 1);
    cfg.blockDim = dim3(block, 1, 1);
    cfg.dynamicSmemBytes = 0;
    cfg.stream = 0;   // legacy default stream (same as <<<>>>)

    cudaLaunchAttribute attrs[1];
    attrs[0].id = cudaLaunchAttributeProgrammaticStreamSerialization;
    attrs[0].val.programmaticStreamSerializationAllowed = 1;
    cfg.attrs = attrs;
    cfg.numAttrs = 1;

    cudaLaunchKernelEx(&cfg, fused_gather_kernel,
                       reinterpret_cast<const float4*>(text),
                       labels,
                       reinterpret_cast<float4*>(out),
                       nhalf);
}

// round 9
// speedup vs baseline: 1.0152x; 1.0152x over previous
#include <cuda_runtime.h>
#include <cuda_fp16.h>
#include <cuda_bf16.h>

// Problem shapes (fixed by the dataset):
//   text:        [16, 2048, 256] f32      d_in[0]
//   const_mat:   [16, 2048, 2048] i32     d_in[1]   (UNUSED: softmax rows sum to 1)
//   const_labels:[16, 2048, 8] i32        d_in[2]
//   emb_table:   [100, 128] f32           d_in[3]
//   attn_W:      [256, 384] f32           d_in[4]   (UNUSED: cancels in softmax)
//   attn_b:      [256] f32                d_in[5]   (UNUSED)
//   fc_W:        [256, 128] f32           d_in[6]
//   fc_b:        [256] f32                d_in[7]
//   out:         [16, 2048, 256] f32
//
// Collapse: out[pos,d] = relu( text[pos,d] + sum_{k=0..7} G[labels[pos,k], d] )
// with G[n,d] = 0.125 * (fc_b[d] + emb_table[n] . fc_W[d]), G stored fp16.
//
// R9: single-wavefront gathers. The R7/R8 profile closes against the B300
// within-LDG replay model (2.07 cyc/wf for every wf after the first of a
// multi-line LDG). Gathers become LDG.32 (one fp16 pair per lane, 32x4B =
// exactly one 128B line = 1 wf, no replays). Row processed in 4 chunks of 64
// dims; 8 label row-bases computed once and reused across chunks.

#define CN    100
#define CD    128
#define DIM   256
#define KLBL  8

__device__ __half g_Gh[CN * DIM];  // 50 KB fp16 table

// ---------------------------------------------------------------------------
// Kernel A: G[n,d] = 0.125 * (fc_b[d] + sum_c emb_table[n,c] * fc_W[d,c]) -> fp16
// ---------------------------------------------------------------------------
__global__ void __launch_bounds__(DIM) build_G_kernel(
    const float* __restrict__ emb_table,
    const float* __restrict__ fc_W,
    const float* __restrict__ fc_b)
{
    __shared__ float se[CD];
    const int n = blockIdx.x;
    const int d = threadIdx.x;
    if (d < CD) se[d] = emb_table[n * CD + d];
    __syncthreads();

    const float4* w4 = reinterpret_cast<const float4*>(fc_W + d * CD);
    float acc = fc_b[d];
    #pragma unroll
    for (int c4 = 0; c4 < CD / 4; c4++) {
        float4 w = __ldg(w4 + c4);
        acc = fmaf(se[c4 * 4 + 0], w.x, acc);
        acc = fmaf(se[c4 * 4 + 1], w.y, acc);
        acc = fmaf(se[c4 * 4 + 2], w.z, acc);
        acc = fmaf(se[c4 * 4 + 3], w.w, acc);
    }
    g_Gh[n * DIM + d] = __float2half_rn(0.125f * acc);
}

// ---------------------------------------------------------------------------
// Kernel B: fused gather-add-relu. One warp per position (gid>>5 = pos,
// lane = fp16-pair slot). 4 chunks of 64 dims; per chunk each lane does
// 8 LDG.32 gathers + 1 LDG.64 text + 1 STG.64 out.
// ---------------------------------------------------------------------------
__device__ __forceinline__ __half2 as_h2(unsigned u) {
    return *reinterpret_cast<const __half2*>(&u);
}

__global__ void __launch_bounds__(256, 5) fused_gather_kernel(
    const float2* __restrict__ text2,   // [npos*128] float2
    const int*    __restrict__ labels,
    float2*       __restrict__ out2,
    int nthreads)   // npos * 32
{
    const int gid = blockIdx.x * blockDim.x + threadIdx.x;
    if (gid >= nthreads) return;

    const int pos  = gid >> 5;   // warp-uniform
    const int lane = gid & 31;   // fp16-pair slot within 64-dim chunk

    const int4* lb = reinterpret_cast<const int4*>(labels) + (pos << 1);
    const int4 l0 = __ldg(lb + 0);
    const int4 l1 = __ldg(lb + 1);

    // Row bases in uint-granularity (row = 128 uints), reused for all chunks.
    const unsigned* __restrict__ Gu = reinterpret_cast<const unsigned*>(g_Gh);
    const int r0 = (l0.x << 7);
    const int r1 = (l0.y << 7);
    const int r2 = (l0.z << 7);
    const int r3 = (l0.w << 7);
    const int r4 = (l1.x << 7);
    const int r5 = (l1.y << 7);
    const int r6 = (l1.z << 7);
    const int r7 = (l1.w << 7);

    const int rowBase = (pos << 7) + lane;   // float2 index of chunk 0

    #pragma unroll
    for (int c = 0; c < 4; c++) {
        const int off = (c << 5) + lane;     // uint offset within G row
        const int io  = rowBase + (c << 5);  // float2 offset in text/out

        // Independent single-wavefront gathers (LDG.32 each).
        const unsigned u0 = __ldg(Gu + r0 + off);
        const unsigned u1 = __ldg(Gu + r1 + off);
        const unsigned u2 = __ldg(Gu + r2 + off);
        const unsigned u3 = __ldg(Gu + r3 + off);
        const unsigned u4 = __ldg(Gu + r4 + off);
        const unsigned u5 = __ldg(Gu + r5 + off);
        const unsigned u6 = __ldg(Gu + r6 + off);
        const unsigned u7 = __ldg(Gu + r7 + off);

        const float2 t = __ldg(text2 + io);

        // One HADD2 level in fp16, then fp32 finish.
        const __half2 p0 = __hadd2(as_h2(u0), as_h2(u1));
        const __half2 p1 = __hadd2(as_h2(u2), as_h2(u3));
        const __half2 p2 = __hadd2(as_h2(u4), as_h2(u5));
        const __half2 p3 = __hadd2(as_h2(u6), as_h2(u7));

        const float2 f0 = __half22float2(p0);
        const float2 f1 = __half22float2(p1);
        const float2 f2 = __half22float2(p2);
        const float2 f3 = __half22float2(p3);

        float2 r;
        r.x = fmaxf(t.x + (f0.x + f1.x) + (f2.x + f3.x), 0.0f);
        r.y = fmaxf(t.y + (f0.y + f1.y) + (f2.y + f3.y), 0.0f);

        __stcs(out2 + io, r);
    }
}

// ---------------------------------------------------------------------------
extern "C" void kernel_launch(void* const* d_in, const int* in_sizes, int n_in,
                              void* d_out, int out_size)
{
    const float* text      = (const float*)d_in[0];
    const int*   labels    = (const int*)  d_in[2];
    const float* emb_table = (const float*)d_in[3];
    const float* fc_W      = (const float*)d_in[6];
    const float* fc_b      = (const float*)d_in[7];
    float*       out       = (float*)d_out;

    const int ntotal   = in_sizes[0];       // 8,388,608
    const int npos     = ntotal / DIM;      // 32,768
    const int nthreads = npos * 32;         // 1,048,576

    build_G_kernel<<<CN, DIM>>>(emb_table, fc_W, fc_b);

    const int block = 256;
    const int grid  = (nthreads + block - 1) / block;   // 4096
    fused_gather_kernel<<<grid, block>>>(
        reinterpret_cast<const float2*>(text),
        labels,
        reinterpret_cast<float2*>(out),
        nthreads);
}